// round 2
// baseline (speedup 1.0000x reference)
#include <cuda_runtime.h>
#include <stdint.h>

#define NMAX 50000
#define EMAX 800000
#define HD   128

// ---------------- scratch (no allocation allowed) ----------------
__device__ float g_h[(size_t)NMAX * HD];
__device__ float g_aggr[(size_t)NMAX * HD];
__device__ float g_z1[(size_t)NMAX * HD];
__device__ int   g_src[EMAX];
__device__ int   g_dst[EMAX];
__device__ int   g_is64;

// ---------------- dtype probe: is edge_index int64 or int32? ----------------
// If int64 (little-endian, values in [0, 50000)), every odd 32-bit word is 0.
// If int32, odd words are random indices — P(all 2048 sampled are 0) ~ 0.
__global__ void k_detect(const int* __restrict__ e32) {
    __shared__ int nonzero;
    if (threadIdx.x == 0) nonzero = 0;
    __syncthreads();
    for (int i = threadIdx.x; i < 2048; i += blockDim.x) {
        if (e32[2 * i + 1] != 0) nonzero = 1;
    }
    __syncthreads();
    if (threadIdx.x == 0) g_is64 = (nonzero == 0) ? 1 : 0;
}

// ---------------- index conversion (handles both dtypes) ----------------
__global__ void k_cvt_idx(const int* __restrict__ e32, int E) {
    int i = blockIdx.x * blockDim.x + threadIdx.x;
    if (i >= E) return;
    if (g_is64) {
        const long long* e64 = (const long long*)e32;
        g_src[i] = (int)e64[i];
        g_dst[i] = (int)e64[(size_t)E + i];
    } else {
        g_src[i] = e32[i];
        g_dst[i] = e32[(size_t)E + i];
    }
}

// ---------------- aggr = (1 + eps[l]) * h ----------------
__global__ void k_init_aggr(const float* __restrict__ eps, int l, int n4) {
    int i = blockIdx.x * blockDim.x + threadIdx.x;
    if (i < n4) {
        float s = 1.0f + __ldg(eps + l);
        float4 v = ((const float4*)g_h)[i];
        v.x *= s; v.y *= s; v.z *= s; v.w *= s;
        ((float4*)g_aggr)[i] = v;
    }
}

// ---------------- edge kernel ----------------
// One warp per edge (grid-stride). W_ee held in registers: lane owns output
// columns [lane*4, lane*4+4). Recomputes ea = edge_attr @ W_ee + b_ee on the
// fly (64 FMA/lane), gathers h[src] (L2-resident), m = relu(h_src+ea)*atten,
// vector reduction-add into aggr[dst].
__global__ void __launch_bounds__(256) k_edge(
    const float* __restrict__ eattr,   // [E,16]
    const float* __restrict__ atten,   // [E]
    const float* __restrict__ Wee,     // [16,128]
    const float* __restrict__ bee,     // [128]
    int E)
{
    const int lane = threadIdx.x & 31;

    // per-lane weight slice: W_ee[k][lane*4 .. lane*4+3] for k = 0..15
    float4 w[16];
#pragma unroll
    for (int k = 0; k < 16; k++)
        w[k] = ((const float4*)Wee)[k * 32 + lane];
    const float4 bb = ((const float4*)bee)[lane];

    const float4* __restrict__ h4 = (const float4*)g_h;

    int warp = (blockIdx.x * blockDim.x + threadIdx.x) >> 5;
    int nwarps = (gridDim.x * blockDim.x) >> 5;

    for (int e = warp; e < E; e += nwarps) {
        int s = g_src[e];
        int d = g_dst[e];
        float at = __ldg(atten + e);

        const float4* ea = (const float4*)(eattr + (size_t)e * 16);
        float4 acc = bb;
#pragma unroll
        for (int kk = 0; kk < 4; kk++) {
            float4 a = __ldg(ea + kk);
            float4 w0 = w[4 * kk + 0], w1 = w[4 * kk + 1];
            float4 w2 = w[4 * kk + 2], w3 = w[4 * kk + 3];
            acc.x = fmaf(a.x, w0.x, fmaf(a.y, w1.x, fmaf(a.z, w2.x, fmaf(a.w, w3.x, acc.x))));
            acc.y = fmaf(a.x, w0.y, fmaf(a.y, w1.y, fmaf(a.z, w2.y, fmaf(a.w, w3.y, acc.y))));
            acc.z = fmaf(a.x, w0.z, fmaf(a.y, w1.z, fmaf(a.z, w2.z, fmaf(a.w, w3.z, acc.z))));
            acc.w = fmaf(a.x, w0.w, fmaf(a.y, w1.w, fmaf(a.z, w2.w, fmaf(a.w, w3.w, acc.w))));
        }

        float4 hs = h4[(size_t)s * 32 + lane];
        float mx = fmaxf(hs.x + acc.x, 0.0f) * at;
        float my = fmaxf(hs.y + acc.y, 0.0f) * at;
        float mz = fmaxf(hs.z + acc.z, 0.0f) * at;
        float mw = fmaxf(hs.w + acc.w, 0.0f) * at;

        float* p = g_aggr + (size_t)d * HD + lane * 4;
        asm volatile("red.global.add.v4.f32 [%0], {%1,%2,%3,%4};"
                     :: "l"(p), "f"(mx), "f"(my), "f"(mz), "f"(mw)
                     : "memory");
    }
}

// ---------------- fused GEMM: out = epilogue(A[M,128] @ W[128,128]) ----------------
// MODE 0: out = A@W + b
// MODE 1: out = relu(BN(A@W + b))
// MODE 2: out = relu(A@W + b)
// Tile: 64(M) x 128(N), TK=32, 256 threads, 4x8 micro-tile per thread.
template <int MODE>
__global__ void __launch_bounds__(256) k_gemm(
    const float* __restrict__ A, const float* __restrict__ W,
    const float* __restrict__ bias,
    const float* __restrict__ gamma, const float* __restrict__ beta,
    const float* __restrict__ mean, const float* __restrict__ var,
    float* __restrict__ out, int M)
{
    __shared__ __align__(16) float  As[32][68];      // [k][m], padded (68*4B = 16B-aligned rows)
    __shared__ __align__(16) float4 Bs[32][32];      // [k][n/4]

    const int tid = threadIdx.x;
    const int bm = blockIdx.x * 64;
    const int mt = tid >> 4;           // 0..15
    const int nt = tid & 15;           // 0..15
    const int m0 = mt * 4;
    const int n0 = nt * 8;

    float acc[4][8];
#pragma unroll
    for (int i = 0; i < 4; i++)
#pragma unroll
        for (int j = 0; j < 8; j++) acc[i][j] = 0.0f;

    for (int kc = 0; kc < 128; kc += 32) {
        // A tile: 64 rows x 32 cols, stored transposed As[k][m]
        {
            int r = tid >> 3;       // 0..31
            int c4 = tid & 7;       // 0..7
#pragma unroll
            for (int p = 0; p < 2; p++) {
                int row = bm + r + p * 32;
                float4 v = make_float4(0.f, 0.f, 0.f, 0.f);
                if (row < M)
                    v = *(const float4*)(A + (size_t)row * 128 + kc + c4 * 4);
                As[c4 * 4 + 0][r + p * 32] = v.x;
                As[c4 * 4 + 1][r + p * 32] = v.y;
                As[c4 * 4 + 2][r + p * 32] = v.z;
                As[c4 * 4 + 3][r + p * 32] = v.w;
            }
        }
        // B tile: 32 rows x 128 cols
        {
            int rr = tid >> 5;      // 0..7
            int cc = tid & 31;      // 0..31
#pragma unroll
            for (int p = 0; p < 4; p++) {
                int k = rr + p * 8;
                Bs[k][cc] = *(const float4*)(W + (size_t)(kc + k) * 128 + cc * 4);
            }
        }
        __syncthreads();

#pragma unroll
        for (int k = 0; k < 32; k++) {
            float4 a = *(const float4*)(&As[k][m0]);
            float4 b0 = Bs[k][nt * 2 + 0];
            float4 b1 = Bs[k][nt * 2 + 1];
            float av[4] = {a.x, a.y, a.z, a.w};
            float bv[8] = {b0.x, b0.y, b0.z, b0.w, b1.x, b1.y, b1.z, b1.w};
#pragma unroll
            for (int i = 0; i < 4; i++)
#pragma unroll
                for (int j = 0; j < 8; j++)
                    acc[i][j] = fmaf(av[i], bv[j], acc[i][j]);
        }
        __syncthreads();
    }

    // epilogue
    float sc[8], sh[8];
#pragma unroll
    for (int j = 0; j < 8; j++) {
        int n = n0 + j;
        float b = __ldg(bias + n);
        if (MODE == 1) {
            float s = __ldg(gamma + n) * rsqrtf(__ldg(var + n) + 1e-5f);
            sc[j] = s;
            sh[j] = __ldg(beta + n) + (b - __ldg(mean + n)) * s;
        } else {
            sc[j] = 1.0f;
            sh[j] = b;
        }
    }
#pragma unroll
    for (int i = 0; i < 4; i++) {
        int row = bm + m0 + i;
        if (row < M) {
            float v[8];
#pragma unroll
            for (int j = 0; j < 8; j++) {
                float t = acc[i][j] * sc[j] + sh[j];
                if (MODE >= 1) t = fmaxf(t, 0.0f);
                v[j] = t;
            }
            float4* o = (float4*)(out + (size_t)row * 128 + n0);
            o[0] = make_float4(v[0], v[1], v[2], v[3]);
            o[1] = make_float4(v[4], v[5], v[6], v[7]);
        }
    }
}

// ---------------- host launcher ----------------
extern "C" void kernel_launch(void* const* d_in, const int* in_sizes, int n_in,
                              void* d_out, int out_size)
{
    const float* x      = (const float*)d_in[0];
    const int*   eidx32 = (const int*)d_in[1];   // int32 OR int64 (probed on device)
    // d_in[2] = batch (unused)
    const float* eattr  = (const float*)d_in[3];
    const float* atten  = (const float*)d_in[4];
    const float* W_enc  = (const float*)d_in[5];
    const float* b_enc  = (const float*)d_in[6];
    const float* W_ee   = (const float*)d_in[7];
    const float* b_ee   = (const float*)d_in[8];
    const float* eps    = (const float*)d_in[9];
    const float* W1     = (const float*)d_in[10];
    const float* b1     = (const float*)d_in[11];
    const float* gam    = (const float*)d_in[12];
    const float* bet    = (const float*)d_in[13];
    const float* mea    = (const float*)d_in[14];
    const float* var    = (const float*)d_in[15];
    const float* W2     = (const float*)d_in[16];
    const float* b2     = (const float*)d_in[17];
    float*       out    = (float*)d_out;

    const int N = in_sizes[0] / HD;     // 50000
    const int E = in_sizes[1] / 2;      // 800000

    void *p_h_, *p_aggr_, *p_z1_;
    cudaGetSymbolAddress(&p_h_, g_h);
    cudaGetSymbolAddress(&p_aggr_, g_aggr);
    cudaGetSymbolAddress(&p_z1_, g_z1);
    float* p_h = (float*)p_h_;
    float* p_aggr = (float*)p_aggr_;
    float* p_z1 = (float*)p_z1_;

    const int gemm_grid = (N + 63) / 64;
    const int n4 = N * (HD / 4);

    // dtype probe + index conversion
    k_detect<<<1, 256>>>(eidx32);
    k_cvt_idx<<<(E + 255) / 256, 256>>>(eidx32, E);

    // node encoder: h = x @ W_enc + b_enc
    k_gemm<0><<<gemm_grid, 256>>>(x, W_enc, b_enc,
                                  nullptr, nullptr, nullptr, nullptr, p_h, N);

    for (int l = 0; l < 3; l++) {
        // aggr = (1+eps)*h
        k_init_aggr<<<(n4 + 255) / 256, 256>>>(eps, l, n4);
        // edge scatter
        k_edge<<<2048, 256>>>(eattr, atten, W_ee, b_ee, E);
        // z1 = relu(BN(aggr @ W1 + b1))
        k_gemm<1><<<gemm_grid, 256>>>(p_aggr, W1 + (size_t)l * HD * HD, b1 + (size_t)l * HD,
                                      gam + (size_t)l * HD, bet + (size_t)l * HD,
                                      mea + (size_t)l * HD, var + (size_t)l * HD,
                                      p_z1, N);
        // h = relu(z1 @ W2 + b2)
        float* dst = (l == 2) ? out : p_h;
        k_gemm<2><<<gemm_grid, 256>>>(p_z1, W2 + (size_t)l * HD * HD, b2 + (size_t)l * HD,
                                      nullptr, nullptr, nullptr, nullptr, dst, N);
    }
}

// round 3
// speedup vs baseline: 1.1411x; 1.1411x over previous
#include <cuda_runtime.h>
#include <stdint.h>

#define NMAX 50000
#define EMAX 800000
#define HD   128

// ---------------- scratch (no allocation allowed) ----------------
__device__ float  g_h[(size_t)NMAX * HD];
__device__ float  g_aggr[(size_t)NMAX * HD];
__device__ float  g_z1[(size_t)NMAX * HD];
__device__ int    g_src[EMAX];
__device__ int    g_dst[EMAX];
__device__ int    g_deg[NMAX];
__device__ int    g_off[NMAX];
__device__ int    g_cursor[NMAX];
__device__ int    g_scan_tmp[NMAX];
__device__ int    g_bsum[256];
__device__ int    g_perm_src[EMAX];
__device__ float  g_perm_at[EMAX];
__device__ float4 g_perm_ea[(size_t)EMAX * 4];
__device__ int    g_is64;

// ---------------- dtype probe: is edge_index int64 or int32? ----------------
__global__ void k_detect(const int* __restrict__ e32) {
    __shared__ int nonzero;
    if (threadIdx.x == 0) nonzero = 0;
    __syncthreads();
    for (int i = threadIdx.x; i < 2048; i += blockDim.x)
        if (e32[2 * i + 1] != 0) nonzero = 1;
    __syncthreads();
    if (threadIdx.x == 0) g_is64 = (nonzero == 0) ? 1 : 0;
}

// ---------------- zero degree histogram ----------------
__global__ void k_zero(int N) {
    int i = blockIdx.x * blockDim.x + threadIdx.x;
    if (i < N) g_deg[i] = 0;
}

// ---------------- index conversion + dst histogram ----------------
__global__ void k_cvt_hist(const int* __restrict__ e32, int E) {
    int i = blockIdx.x * blockDim.x + threadIdx.x;
    if (i >= E) return;
    int s, d;
    if (g_is64) {
        const long long* e64 = (const long long*)e32;
        s = (int)e64[i];
        d = (int)e64[(size_t)E + i];
    } else {
        s = e32[i];
        d = e32[(size_t)E + i];
    }
    g_src[i] = s;
    g_dst[i] = d;
    atomicAdd(&g_deg[d], 1);
}

// ---------------- 2-level exclusive scan of g_deg -> g_off ----------------
__global__ void k_scan1(int N) {
    __shared__ int sh[256];
    int t = threadIdx.x;
    int i = blockIdx.x * 256 + t;
    int v = (i < N) ? g_deg[i] : 0;
    sh[t] = v;
    __syncthreads();
#pragma unroll
    for (int o = 1; o < 256; o <<= 1) {
        int add = (t >= o) ? sh[t - o] : 0;
        __syncthreads();
        sh[t] += add;
        __syncthreads();
    }
    if (i < N) g_scan_tmp[i] = sh[t];          // inclusive within block
    if (t == 255) g_bsum[blockIdx.x] = sh[255];
}

__global__ void k_scan2(int nb) {
    __shared__ int sh[256];
    int t = threadIdx.x;
    int v = (t < nb) ? g_bsum[t] : 0;
    sh[t] = v;
    __syncthreads();
#pragma unroll
    for (int o = 1; o < 256; o <<= 1) {
        int add = (t >= o) ? sh[t - o] : 0;
        __syncthreads();
        sh[t] += add;
        __syncthreads();
    }
    g_bsum[t] = sh[t];                          // inclusive scan of block sums
}

__global__ void k_scan3(int N) {
    int i = blockIdx.x * 256 + threadIdx.x;
    if (i >= N) return;
    int base = (blockIdx.x > 0) ? g_bsum[blockIdx.x - 1] : 0;
    int excl = g_scan_tmp[i] - g_deg[i] + base;
    g_off[i] = excl;
    g_cursor[i] = excl;
}

// ---------------- fill CSR: permute src/atten/eattr into dst-order ----------------
__global__ void k_fill(const float* __restrict__ eattr,
                       const float* __restrict__ atten, int E) {
    int e = blockIdx.x * blockDim.x + threadIdx.x;
    if (e >= E) return;
    int d = g_dst[e];
    int pos = atomicAdd(&g_cursor[d], 1);
    g_perm_src[pos] = g_src[e];
    g_perm_at[pos] = __ldg(atten + e);
    const float4* s4 = (const float4*)(eattr + (size_t)e * 16);
    float4* d4 = &g_perm_ea[(size_t)pos * 4];
    d4[0] = __ldg(s4 + 0);
    d4[1] = __ldg(s4 + 1);
    d4[2] = __ldg(s4 + 2);
    d4[3] = __ldg(s4 + 3);
}

// ---------------- per-node aggregation (no atomics) ----------------
// One warp per node. Lane owns cols [lane*4, lane*4+4). W_ee in registers.
// aggr[node] = (1+eps)*h[node] + sum_{e->node} relu(h[src]+ea)*at

#define KSTEP(R, A, Wa, Wb, Wc, Wd)                                                     \
    R.x = fmaf(A.x, Wa.x, fmaf(A.y, Wb.x, fmaf(A.z, Wc.x, fmaf(A.w, Wd.x, R.x))));     \
    R.y = fmaf(A.x, Wa.y, fmaf(A.y, Wb.y, fmaf(A.z, Wc.y, fmaf(A.w, Wd.y, R.y))));     \
    R.z = fmaf(A.x, Wa.z, fmaf(A.y, Wb.z, fmaf(A.z, Wc.z, fmaf(A.w, Wd.z, R.z))));     \
    R.w = fmaf(A.x, Wa.w, fmaf(A.y, Wb.w, fmaf(A.z, Wc.w, fmaf(A.w, Wd.w, R.w))))

#define EAMV(R, A0, A1, A2, A3)              \
    R = bb;                                  \
    KSTEP(R, A0, w0, w1, w2, w3);            \
    KSTEP(R, A1, w4, w5, w6, w7);            \
    KSTEP(R, A2, w8, w9, w10, w11);          \
    KSTEP(R, A3, w12, w13, w14, w15)

#define ACCUM(ACC, H, R, AT)                       \
    ACC.x += fmaxf(H.x + R.x, 0.0f) * AT;          \
    ACC.y += fmaxf(H.y + R.y, 0.0f) * AT;          \
    ACC.z += fmaxf(H.z + R.z, 0.0f) * AT;          \
    ACC.w += fmaxf(H.w + R.w, 0.0f) * AT

__global__ void __launch_bounds__(128) k_node(
    const float* __restrict__ Wee, const float* __restrict__ bee,
    const float* __restrict__ eps, int l, int N)
{
    const int lane = threadIdx.x & 31;
    const int warp = threadIdx.x >> 5;
    const int node = blockIdx.x * 4 + warp;

    const float4* __restrict__ Wv = (const float4*)Wee;
    float4 w0 = Wv[0 * 32 + lane],   w1 = Wv[1 * 32 + lane];
    float4 w2 = Wv[2 * 32 + lane],   w3 = Wv[3 * 32 + lane];
    float4 w4 = Wv[4 * 32 + lane],   w5 = Wv[5 * 32 + lane];
    float4 w6 = Wv[6 * 32 + lane],   w7 = Wv[7 * 32 + lane];
    float4 w8 = Wv[8 * 32 + lane],   w9 = Wv[9 * 32 + lane];
    float4 w10 = Wv[10 * 32 + lane], w11 = Wv[11 * 32 + lane];
    float4 w12 = Wv[12 * 32 + lane], w13 = Wv[13 * 32 + lane];
    float4 w14 = Wv[14 * 32 + lane], w15 = Wv[15 * 32 + lane];
    const float4 bb = ((const float4*)bee)[lane];

    if (node >= N) return;

    const float4* __restrict__ h4 = (const float4*)g_h;

    const int start = g_off[node];
    const int deg = g_deg[node];
    const int end = start + deg;

    const float s1p = 1.0f + __ldg(eps + l);
    float4 hn = h4[(size_t)node * 32 + lane];
    float4 acc = make_float4(hn.x * s1p, hn.y * s1p, hn.z * s1p, hn.w * s1p);

    int j = start;
    for (; j + 2 <= end; j += 2) {
        int s0 = g_perm_src[j];
        int s1 = g_perm_src[j + 1];
        float at0 = g_perm_at[j];
        float at1 = g_perm_at[j + 1];
        const float4* ep = &g_perm_ea[(size_t)j * 4];
        float4 a00 = ep[0], a01 = ep[1], a02 = ep[2], a03 = ep[3];
        float4 a10 = ep[4], a11 = ep[5], a12 = ep[6], a13 = ep[7];
        float4 h0 = h4[(size_t)s0 * 32 + lane];
        float4 h1 = h4[(size_t)s1 * 32 + lane];
        float4 r0, r1;
        EAMV(r0, a00, a01, a02, a03);
        EAMV(r1, a10, a11, a12, a13);
        ACCUM(acc, h0, r0, at0);
        ACCUM(acc, h1, r1, at1);
    }
    if (j < end) {
        int s0 = g_perm_src[j];
        float at0 = g_perm_at[j];
        const float4* ep = &g_perm_ea[(size_t)j * 4];
        float4 a00 = ep[0], a01 = ep[1], a02 = ep[2], a03 = ep[3];
        float4 h0 = h4[(size_t)s0 * 32 + lane];
        float4 r0;
        EAMV(r0, a00, a01, a02, a03);
        ACCUM(acc, h0, r0, at0);
    }

    ((float4*)g_aggr)[(size_t)node * 32 + lane] = acc;
}

// ---------------- fused GEMM: out = epilogue(A[M,128] @ W[128,128]) ----------------
// MODE 0: out = A@W + b ; MODE 1: relu(BN(A@W+b)) ; MODE 2: relu(A@W+b)
template <int MODE>
__global__ void __launch_bounds__(256) k_gemm(
    const float* __restrict__ A, const float* __restrict__ W,
    const float* __restrict__ bias,
    const float* __restrict__ gamma, const float* __restrict__ beta,
    const float* __restrict__ mean, const float* __restrict__ var,
    float* __restrict__ out, int M)
{
    __shared__ __align__(16) float  As[32][68];
    __shared__ __align__(16) float4 Bs[32][32];

    const int tid = threadIdx.x;
    const int bm = blockIdx.x * 64;
    const int mt = tid >> 4;
    const int nt = tid & 15;
    const int m0 = mt * 4;
    const int n0 = nt * 8;

    float acc[4][8];
#pragma unroll
    for (int i = 0; i < 4; i++)
#pragma unroll
        for (int j = 0; j < 8; j++) acc[i][j] = 0.0f;

    for (int kc = 0; kc < 128; kc += 32) {
        {
            int r = tid >> 3;
            int c4 = tid & 7;
#pragma unroll
            for (int p = 0; p < 2; p++) {
                int row = bm + r + p * 32;
                float4 v = make_float4(0.f, 0.f, 0.f, 0.f);
                if (row < M)
                    v = *(const float4*)(A + (size_t)row * 128 + kc + c4 * 4);
                As[c4 * 4 + 0][r + p * 32] = v.x;
                As[c4 * 4 + 1][r + p * 32] = v.y;
                As[c4 * 4 + 2][r + p * 32] = v.z;
                As[c4 * 4 + 3][r + p * 32] = v.w;
            }
        }
        {
            int rr = tid >> 5;
            int cc = tid & 31;
#pragma unroll
            for (int p = 0; p < 4; p++) {
                int k = rr + p * 8;
                Bs[k][cc] = *(const float4*)(W + (size_t)(kc + k) * 128 + cc * 4);
            }
        }
        __syncthreads();

#pragma unroll
        for (int k = 0; k < 32; k++) {
            float4 a = *(const float4*)(&As[k][m0]);
            float4 b0 = Bs[k][nt * 2 + 0];
            float4 b1 = Bs[k][nt * 2 + 1];
            float av[4] = {a.x, a.y, a.z, a.w};
            float bv[8] = {b0.x, b0.y, b0.z, b0.w, b1.x, b1.y, b1.z, b1.w};
#pragma unroll
            for (int i = 0; i < 4; i++)
#pragma unroll
                for (int j = 0; j < 8; j++)
                    acc[i][j] = fmaf(av[i], bv[j], acc[i][j]);
        }
        __syncthreads();
    }

    float sc[8], sh[8];
#pragma unroll
    for (int j = 0; j < 8; j++) {
        int n = n0 + j;
        float b = __ldg(bias + n);
        if (MODE == 1) {
            float s = __ldg(gamma + n) * rsqrtf(__ldg(var + n) + 1e-5f);
            sc[j] = s;
            sh[j] = __ldg(beta + n) + (b - __ldg(mean + n)) * s;
        } else {
            sc[j] = 1.0f;
            sh[j] = b;
        }
    }
#pragma unroll
    for (int i = 0; i < 4; i++) {
        int row = bm + m0 + i;
        if (row < M) {
            float v[8];
#pragma unroll
            for (int j = 0; j < 8; j++) {
                float t = acc[i][j] * sc[j] + sh[j];
                if (MODE >= 1) t = fmaxf(t, 0.0f);
                v[j] = t;
            }
            float4* o = (float4*)(out + (size_t)row * 128 + n0);
            o[0] = make_float4(v[0], v[1], v[2], v[3]);
            o[1] = make_float4(v[4], v[5], v[6], v[7]);
        }
    }
}

// ---------------- host launcher ----------------
extern "C" void kernel_launch(void* const* d_in, const int* in_sizes, int n_in,
                              void* d_out, int out_size)
{
    const float* x      = (const float*)d_in[0];
    const int*   eidx32 = (const int*)d_in[1];
    // d_in[2] = batch (unused)
    const float* eattr  = (const float*)d_in[3];
    const float* atten  = (const float*)d_in[4];
    const float* W_enc  = (const float*)d_in[5];
    const float* b_enc  = (const float*)d_in[6];
    const float* W_ee   = (const float*)d_in[7];
    const float* b_ee   = (const float*)d_in[8];
    const float* eps    = (const float*)d_in[9];
    const float* W1     = (const float*)d_in[10];
    const float* b1     = (const float*)d_in[11];
    const float* gam    = (const float*)d_in[12];
    const float* bet    = (const float*)d_in[13];
    const float* mea    = (const float*)d_in[14];
    const float* var    = (const float*)d_in[15];
    const float* W2     = (const float*)d_in[16];
    const float* b2     = (const float*)d_in[17];
    float*       out    = (float*)d_out;

    const int N = in_sizes[0] / HD;     // 50000
    const int E = in_sizes[1] / 2;      // 800000

    void *p_h_, *p_aggr_, *p_z1_;
    cudaGetSymbolAddress(&p_h_, g_h);
    cudaGetSymbolAddress(&p_aggr_, g_aggr);
    cudaGetSymbolAddress(&p_z1_, g_z1);
    float* p_h = (float*)p_h_;
    float* p_aggr = (float*)p_aggr_;
    float* p_z1 = (float*)p_z1_;

    const int gemm_grid = (N + 63) / 64;
    const int nb = (N + 255) / 256;     // scan blocks (196)

    // CSR build
    k_detect<<<1, 256>>>(eidx32);
    k_zero<<<nb, 256>>>(N);
    k_cvt_hist<<<(E + 255) / 256, 256>>>(eidx32, E);
    k_scan1<<<nb, 256>>>(N);
    k_scan2<<<1, 256>>>(nb);
    k_scan3<<<nb, 256>>>(N);
    k_fill<<<(E + 127) / 128, 128>>>(eattr, atten, E);

    // node encoder: h = x @ W_enc + b_enc
    k_gemm<0><<<gemm_grid, 256>>>(x, W_enc, b_enc,
                                  nullptr, nullptr, nullptr, nullptr, p_h, N);

    for (int l = 0; l < 3; l++) {
        k_node<<<(N + 3) / 4, 128>>>(W_ee, b_ee, eps, l, N);
        k_gemm<1><<<gemm_grid, 256>>>(p_aggr, W1 + (size_t)l * HD * HD, b1 + (size_t)l * HD,
                                      gam + (size_t)l * HD, bet + (size_t)l * HD,
                                      mea + (size_t)l * HD, var + (size_t)l * HD,
                                      p_z1, N);
        float* dst = (l == 2) ? out : p_h;
        k_gemm<2><<<gemm_grid, 256>>>(p_z1, W2 + (size_t)l * HD * HD, b2 + (size_t)l * HD,
                                      nullptr, nullptr, nullptr, nullptr, dst, N);
    }
}

// round 4
// speedup vs baseline: 1.5997x; 1.4019x over previous
#include <cuda_runtime.h>
#include <stdint.h>

#define NMAX 50000
#define EMAX 800000
#define HD   128

// ---------------- scratch (no allocation allowed) ----------------
__device__ float  g_h[(size_t)NMAX * HD];
__device__ float  g_aggr[(size_t)NMAX * HD];
__device__ float  g_z1[(size_t)NMAX * HD];
__device__ int    g_src[EMAX];
__device__ int    g_dst[EMAX];
__device__ int    g_deg[NMAX];
__device__ int    g_off[NMAX];
__device__ int    g_cursor[NMAX];
__device__ int    g_scan_tmp[NMAX];
__device__ int    g_bsum[256];
__device__ int    g_perm_src[EMAX];
__device__ float  g_perm_at[EMAX];
__device__ float4 g_perm_attr[(size_t)EMAX * 4];       // permuted edge_attr [E,16]
__device__ float4 g_ea[(size_t)EMAX * 32];             // precomputed ea [E,128] (409.6 MB)
__device__ int    g_is64;

// ---------------- zero histogram + dtype probe ----------------
__global__ void k_zero_detect(const int* __restrict__ e32, int N) {
    int i = blockIdx.x * blockDim.x + threadIdx.x;
    if (i < N) g_deg[i] = 0;
    if (blockIdx.x == 0) {
        __shared__ int nonzero;
        if (threadIdx.x == 0) nonzero = 0;
        __syncthreads();
        for (int k = threadIdx.x; k < 2048; k += blockDim.x)
            if (e32[2 * k + 1] != 0) nonzero = 1;
        __syncthreads();
        if (threadIdx.x == 0) g_is64 = (nonzero == 0) ? 1 : 0;
    }
}

// ---------------- index conversion + dst histogram ----------------
__global__ void k_cvt_hist(const int* __restrict__ e32, int E) {
    int i = blockIdx.x * blockDim.x + threadIdx.x;
    if (i >= E) return;
    int s, d;
    if (g_is64) {
        const long long* e64 = (const long long*)e32;
        s = (int)e64[i];
        d = (int)e64[(size_t)E + i];
    } else {
        s = e32[i];
        d = e32[(size_t)E + i];
    }
    g_src[i] = s;
    g_dst[i] = d;
    atomicAdd(&g_deg[d], 1);
}

// ---------------- 2-level exclusive scan of g_deg -> g_off ----------------
__global__ void k_scan1(int N) {
    __shared__ int sh[256];
    int t = threadIdx.x;
    int i = blockIdx.x * 256 + t;
    int v = (i < N) ? g_deg[i] : 0;
    sh[t] = v;
    __syncthreads();
#pragma unroll
    for (int o = 1; o < 256; o <<= 1) {
        int add = (t >= o) ? sh[t - o] : 0;
        __syncthreads();
        sh[t] += add;
        __syncthreads();
    }
    if (i < N) g_scan_tmp[i] = sh[t];
    if (t == 255) g_bsum[blockIdx.x] = sh[255];
}

__global__ void k_scan2(int nb) {
    __shared__ int sh[256];
    int t = threadIdx.x;
    int v = (t < nb) ? g_bsum[t] : 0;
    sh[t] = v;
    __syncthreads();
#pragma unroll
    for (int o = 1; o < 256; o <<= 1) {
        int add = (t >= o) ? sh[t - o] : 0;
        __syncthreads();
        sh[t] += add;
        __syncthreads();
    }
    g_bsum[t] = sh[t];
}

__global__ void k_scan3(int N) {
    int i = blockIdx.x * 256 + threadIdx.x;
    if (i >= N) return;
    int base = (blockIdx.x > 0) ? g_bsum[blockIdx.x - 1] : 0;
    int excl = g_scan_tmp[i] - g_deg[i] + base;
    g_off[i] = excl;
    g_cursor[i] = excl;
}

// ---------------- fill CSR: permute src/atten/edge_attr into dst-order ----------------
__global__ void k_fill(const float* __restrict__ eattr,
                       const float* __restrict__ atten, int E) {
    int e = blockIdx.x * blockDim.x + threadIdx.x;
    if (e >= E) return;
    int d = g_dst[e];
    int pos = atomicAdd(&g_cursor[d], 1);
    g_perm_src[pos] = g_src[e];
    g_perm_at[pos] = __ldg(atten + e);
    const float4* s4 = (const float4*)(eattr + (size_t)e * 16);
    float4* d4 = &g_perm_attr[(size_t)pos * 4];
    d4[0] = __ldg(s4 + 0);
    d4[1] = __ldg(s4 + 1);
    d4[2] = __ldg(s4 + 2);
    d4[3] = __ldg(s4 + 3);
}

// ---------------- matvec helpers ----------------
#define KSTEP(R, A, Wa, Wb, Wc, Wd)                                                     \
    R.x = fmaf(A.x, Wa.x, fmaf(A.y, Wb.x, fmaf(A.z, Wc.x, fmaf(A.w, Wd.x, R.x))));     \
    R.y = fmaf(A.x, Wa.y, fmaf(A.y, Wb.y, fmaf(A.z, Wc.y, fmaf(A.w, Wd.y, R.y))));     \
    R.z = fmaf(A.x, Wa.z, fmaf(A.y, Wb.z, fmaf(A.z, Wc.z, fmaf(A.w, Wd.z, R.z))));     \
    R.w = fmaf(A.x, Wa.w, fmaf(A.y, Wb.w, fmaf(A.z, Wc.w, fmaf(A.w, Wd.w, R.w))))

// ---------------- precompute ea = perm_attr @ W_ee + b_ee (ONCE) ----------------
// One warp per edge (grid-stride). Lane owns output cols [lane*4, lane*4+4).
__global__ void __launch_bounds__(256) k_ea(
    const float* __restrict__ Wee, const float* __restrict__ bee, int E)
{
    const int lane = threadIdx.x & 31;

    float4 w[16];
#pragma unroll
    for (int k = 0; k < 16; k++)
        w[k] = ((const float4*)Wee)[k * 32 + lane];
    const float4 bb = ((const float4*)bee)[lane];

    int warp = (blockIdx.x * blockDim.x + threadIdx.x) >> 5;
    int nwarps = (gridDim.x * blockDim.x) >> 5;

    for (int e = warp; e < E; e += nwarps) {
        const float4* ap = &g_perm_attr[(size_t)e * 4];
        float4 a0 = ap[0], a1 = ap[1], a2 = ap[2], a3 = ap[3];
        float4 r = bb;
        KSTEP(r, a0, w[0], w[1], w[2], w[3]);
        KSTEP(r, a1, w[4], w[5], w[6], w[7]);
        KSTEP(r, a2, w[8], w[9], w[10], w[11]);
        KSTEP(r, a3, w[12], w[13], w[14], w[15]);
        g_ea[(size_t)e * 32 + lane] = r;
    }
}

// ---------------- per-node aggregation (no atomics, streaming) ----------------
// One warp per node. Lane owns cols [lane*4, lane*4+4).
// aggr[node] = (1+eps)*h[node] + sum_{e->node} relu(h[src]+ea[e])*at[e]
__global__ void __launch_bounds__(256) k_node(
    const float* __restrict__ eps, int l, int N)
{
    const int lane = threadIdx.x & 31;
    const int warp = threadIdx.x >> 5;
    const int node = blockIdx.x * 8 + warp;
    if (node >= N) return;

    const float4* __restrict__ h4 = (const float4*)g_h;
    const float4* __restrict__ ea4 = g_ea;

    const int start = g_off[node];
    const int end = start + g_deg[node];

    const float s1p = 1.0f + __ldg(eps + l);
    float4 hn = h4[(size_t)node * 32 + lane];
    float4 acc = make_float4(hn.x * s1p, hn.y * s1p, hn.z * s1p, hn.w * s1p);

    int j = start;
#pragma unroll 1
    for (; j + 4 <= end; j += 4) {
        int s0 = g_perm_src[j + 0], s1 = g_perm_src[j + 1];
        int s2 = g_perm_src[j + 2], s3 = g_perm_src[j + 3];
        float at0 = g_perm_at[j + 0], at1 = g_perm_at[j + 1];
        float at2 = g_perm_at[j + 2], at3 = g_perm_at[j + 3];
        float4 e0 = ea4[(size_t)(j + 0) * 32 + lane];
        float4 e1 = ea4[(size_t)(j + 1) * 32 + lane];
        float4 e2 = ea4[(size_t)(j + 2) * 32 + lane];
        float4 e3 = ea4[(size_t)(j + 3) * 32 + lane];
        float4 h0 = h4[(size_t)s0 * 32 + lane];
        float4 h1 = h4[(size_t)s1 * 32 + lane];
        float4 h2 = h4[(size_t)s2 * 32 + lane];
        float4 h3 = h4[(size_t)s3 * 32 + lane];
        acc.x += fmaxf(h0.x + e0.x, 0.f) * at0 + fmaxf(h1.x + e1.x, 0.f) * at1
               + fmaxf(h2.x + e2.x, 0.f) * at2 + fmaxf(h3.x + e3.x, 0.f) * at3;
        acc.y += fmaxf(h0.y + e0.y, 0.f) * at0 + fmaxf(h1.y + e1.y, 0.f) * at1
               + fmaxf(h2.y + e2.y, 0.f) * at2 + fmaxf(h3.y + e3.y, 0.f) * at3;
        acc.z += fmaxf(h0.z + e0.z, 0.f) * at0 + fmaxf(h1.z + e1.z, 0.f) * at1
               + fmaxf(h2.z + e2.z, 0.f) * at2 + fmaxf(h3.z + e3.z, 0.f) * at3;
        acc.w += fmaxf(h0.w + e0.w, 0.f) * at0 + fmaxf(h1.w + e1.w, 0.f) * at1
               + fmaxf(h2.w + e2.w, 0.f) * at2 + fmaxf(h3.w + e3.w, 0.f) * at3;
    }
    for (; j < end; j++) {
        int s0 = g_perm_src[j];
        float at0 = g_perm_at[j];
        float4 e0 = ea4[(size_t)j * 32 + lane];
        float4 h0 = h4[(size_t)s0 * 32 + lane];
        acc.x += fmaxf(h0.x + e0.x, 0.f) * at0;
        acc.y += fmaxf(h0.y + e0.y, 0.f) * at0;
        acc.z += fmaxf(h0.z + e0.z, 0.f) * at0;
        acc.w += fmaxf(h0.w + e0.w, 0.f) * at0;
    }

    ((float4*)g_aggr)[(size_t)node * 32 + lane] = acc;
}

// ---------------- fused GEMM: out = epilogue(A[M,128] @ W[128,128]) ----------------
// MODE 0: out = A@W + b ; MODE 1: relu(BN(A@W+b)) ; MODE 2: relu(A@W+b)
template <int MODE>
__global__ void __launch_bounds__(256) k_gemm(
    const float* __restrict__ A, const float* __restrict__ W,
    const float* __restrict__ bias,
    const float* __restrict__ gamma, const float* __restrict__ beta,
    const float* __restrict__ mean, const float* __restrict__ var,
    float* __restrict__ out, int M)
{
    __shared__ __align__(16) float  As[32][68];
    __shared__ __align__(16) float4 Bs[32][32];

    const int tid = threadIdx.x;
    const int bm = blockIdx.x * 64;
    const int mt = tid >> 4;
    const int nt = tid & 15;
    const int m0 = mt * 4;
    const int n0 = nt * 8;

    float acc[4][8];
#pragma unroll
    for (int i = 0; i < 4; i++)
#pragma unroll
        for (int j = 0; j < 8; j++) acc[i][j] = 0.0f;

    for (int kc = 0; kc < 128; kc += 32) {
        {
            int r = tid >> 3;
            int c4 = tid & 7;
#pragma unroll
            for (int p = 0; p < 2; p++) {
                int row = bm + r + p * 32;
                float4 v = make_float4(0.f, 0.f, 0.f, 0.f);
                if (row < M)
                    v = *(const float4*)(A + (size_t)row * 128 + kc + c4 * 4);
                As[c4 * 4 + 0][r + p * 32] = v.x;
                As[c4 * 4 + 1][r + p * 32] = v.y;
                As[c4 * 4 + 2][r + p * 32] = v.z;
                As[c4 * 4 + 3][r + p * 32] = v.w;
            }
        }
        {
            int rr = tid >> 5;
            int cc = tid & 31;
#pragma unroll
            for (int p = 0; p < 4; p++) {
                int k = rr + p * 8;
                Bs[k][cc] = *(const float4*)(W + (size_t)(kc + k) * 128 + cc * 4);
            }
        }
        __syncthreads();

#pragma unroll
        for (int k = 0; k < 32; k++) {
            float4 a = *(const float4*)(&As[k][m0]);
            float4 b0 = Bs[k][nt * 2 + 0];
            float4 b1 = Bs[k][nt * 2 + 1];
            float av[4] = {a.x, a.y, a.z, a.w};
            float bv[8] = {b0.x, b0.y, b0.z, b0.w, b1.x, b1.y, b1.z, b1.w};
#pragma unroll
            for (int i = 0; i < 4; i++)
#pragma unroll
                for (int j = 0; j < 8; j++)
                    acc[i][j] = fmaf(av[i], bv[j], acc[i][j]);
        }
        __syncthreads();
    }

    float sc[8], sh[8];
#pragma unroll
    for (int j = 0; j < 8; j++) {
        int n = n0 + j;
        float b = __ldg(bias + n);
        if (MODE == 1) {
            float s = __ldg(gamma + n) * rsqrtf(__ldg(var + n) + 1e-5f);
            sc[j] = s;
            sh[j] = __ldg(beta + n) + (b - __ldg(mean + n)) * s;
        } else {
            sc[j] = 1.0f;
            sh[j] = b;
        }
    }
#pragma unroll
    for (int i = 0; i < 4; i++) {
        int row = bm + m0 + i;
        if (row < M) {
            float v[8];
#pragma unroll
            for (int j = 0; j < 8; j++) {
                float t = acc[i][j] * sc[j] + sh[j];
                if (MODE >= 1) t = fmaxf(t, 0.0f);
                v[j] = t;
            }
            float4* o = (float4*)(out + (size_t)row * 128 + n0);
            o[0] = make_float4(v[0], v[1], v[2], v[3]);
            o[1] = make_float4(v[4], v[5], v[6], v[7]);
        }
    }
}

// ---------------- host launcher ----------------
extern "C" void kernel_launch(void* const* d_in, const int* in_sizes, int n_in,
                              void* d_out, int out_size)
{
    const float* x      = (const float*)d_in[0];
    const int*   eidx32 = (const int*)d_in[1];
    // d_in[2] = batch (unused)
    const float* eattr  = (const float*)d_in[3];
    const float* atten  = (const float*)d_in[4];
    const float* W_enc  = (const float*)d_in[5];
    const float* b_enc  = (const float*)d_in[6];
    const float* W_ee   = (const float*)d_in[7];
    const float* b_ee   = (const float*)d_in[8];
    const float* eps    = (const float*)d_in[9];
    const float* W1     = (const float*)d_in[10];
    const float* b1     = (const float*)d_in[11];
    const float* gam    = (const float*)d_in[12];
    const float* bet    = (const float*)d_in[13];
    const float* mea    = (const float*)d_in[14];
    const float* var    = (const float*)d_in[15];
    const float* W2     = (const float*)d_in[16];
    const float* b2     = (const float*)d_in[17];
    float*       out    = (float*)d_out;

    const int N = in_sizes[0] / HD;     // 50000
    const int E = in_sizes[1] / 2;      // 800000

    void *p_h_, *p_aggr_, *p_z1_;
    cudaGetSymbolAddress(&p_h_, g_h);
    cudaGetSymbolAddress(&p_aggr_, g_aggr);
    cudaGetSymbolAddress(&p_z1_, g_z1);
    float* p_h = (float*)p_h_;
    float* p_aggr = (float*)p_aggr_;
    float* p_z1 = (float*)p_z1_;

    const int gemm_grid = (N + 63) / 64;
    const int nb = (N + 255) / 256;

    // CSR build (launches 0-4)
    k_zero_detect<<<nb, 256>>>(eidx32, N);
    k_cvt_hist<<<(E + 255) / 256, 256>>>(eidx32, E);
    k_scan1<<<nb, 256>>>(N);
    k_scan2<<<1, 256>>>(nb);
    k_scan3<<<nb, 256>>>(N);

    // launch 5 (profiled by ncu -s 5 -c 1): encoder GEMM
    k_gemm<0><<<gemm_grid, 256>>>(x, W_enc, b_enc,
                                  nullptr, nullptr, nullptr, nullptr, p_h, N);

    // permute edge data, then precompute ea once
    k_fill<<<(E + 127) / 128, 128>>>(eattr, atten, E);
    k_ea<<<2048, 256>>>(W_ee, b_ee, E);

    for (int l = 0; l < 3; l++) {
        k_node<<<(N + 7) / 8, 256>>>(eps, l, N);
        k_gemm<1><<<gemm_grid, 256>>>(p_aggr, W1 + (size_t)l * HD * HD, b1 + (size_t)l * HD,
                                      gam + (size_t)l * HD, bet + (size_t)l * HD,
                                      mea + (size_t)l * HD, var + (size_t)l * HD,
                                      p_z1, N);
        float* dst = (l == 2) ? out : p_h;
        k_gemm<2><<<gemm_grid, 256>>>(p_z1, W2 + (size_t)l * HD * HD, b2 + (size_t)l * HD,
                                      nullptr, nullptr, nullptr, nullptr, dst, N);
    }
}